// round 12
// baseline (speedup 1.0000x reference)
#include <cuda_runtime.h>
#include <cuda_fp16.h>

#define NPTS    512
#define NCH     64
#define THREADS 1024
#define WARPS   (THREADS / 32)
#define U       4                         // points per warp per iteration
#define LINE_HALFS (NPTS * NCH)           // 32768 halves per line
#define SMEM_BYTES (3 * LINE_HALFS * 2)   // 196608 B

__global__ __launch_bounds__(THREADS, 1)
void triline_kernel(const float* __restrict__ coords,
                    const float* __restrict__ xl,
                    const float* __restrict__ yl,
                    const float* __restrict__ zl,
                    const float* __restrict__ grid,
                    float* __restrict__ out,
                    int B)
{
    extern __shared__ __half2 smem2[];    // 3 lines x 16384 half2

    // ---- cooperative fill: fp32 global -> fp16 smem (contiguous, coalesced) ----
    {
        const float* srcs[3] = { xl, yl, zl };
        #pragma unroll
        for (int a = 0; a < 3; a++) {
            const float4* src = reinterpret_cast<const float4*>(srcs[a]);
            __half2*      dst = smem2 + a * (LINE_HALFS / 2);
            for (int i = threadIdx.x; i < LINE_HALFS / 4; i += THREADS) {
                const float4 f = src[i];
                dst[2 * i    ] = __floats2half2_rn(f.x, f.y);
                dst[2 * i + 1] = __floats2half2_rn(f.z, f.w);
            }
        }
    }

    const float g0     = grid[0];
    const float inv_dg = 1.0f / (grid[1] - grid[0]);
    __syncthreads();

    const int lane = threadIdx.x & 31;
    const int wid  = threadIdx.x >> 5;
    const int g    = lane >> 3;           // point group 0..3 within warp
    const int ch   = (lane & 7) << 3;     // channel offset in halves (8 ch per lane)

    const __half* sbase = reinterpret_cast<const __half*>(smem2);

    const int stride = gridDim.x * WARPS * U;
    int p0 = (blockIdx.x * WARPS + wid) * U;

    // Per-lane direct coord prefetch for THIS lane's point (8-lane broadcast,
    // coalesces to the same 48B the old cooperative load touched). No shuffles.
    float c0 = 0.f, c1 = 0.f, c2 = 0.f;
    if (p0 < B) {
        const float* cp = coords + 3 * (p0 + g);
        c0 = __ldg(cp + 0);  c1 = __ldg(cp + 1);  c2 = __ldg(cp + 2);
    }

    while (p0 < B) {
        const int pn = p0 + stride;

        // Prefetch next iteration's coords (hide DRAM latency behind this body)
        float c0n = 0.f, c1n = 0.f, c2n = 0.f;
        if (pn < B) {
            const float* cp = coords + 3 * (pn + g);
            c0n = __ldg(cp + 0);  c1n = __ldg(cp + 1);  c2n = __ldg(cp + 2);
        }

        // ---- index math for all 3 axes (lane-local, no shuffles) ----
        float pos0 = (c0 - g0) * inv_dg;
        float pos1 = (c1 - g0) * inv_dg;
        float pos2 = (c2 - g0) * inv_dg;
        int i0 = max(0, min((int)floorf(pos0), NPTS - 2));
        int i1 = max(0, min((int)floorf(pos1), NPTS - 2));
        int i2 = max(0, min((int)floorf(pos2), NPTS - 2));
        const __half2 w0 = __float2half2_rn(pos0 - (float)i0);
        const __half2 w1 = __float2half2_rn(pos1 - (float)i1);
        const __half2 w2 = __float2half2_rn(pos2 - (float)i2);

        // ---- issue all 6 LDS.128 back-to-back (max MLP) ----
        const __half* bx = sbase + 0 * LINE_HALFS + i0 * NCH + ch;
        const __half* by = sbase + 1 * LINE_HALFS + i1 * NCH + ch;
        const __half* bz = sbase + 2 * LINE_HALFS + i2 * NCH + ch;
        const uint4 x0 = *reinterpret_cast<const uint4*>(bx);
        const uint4 x1 = *reinterpret_cast<const uint4*>(bx + NCH);
        const uint4 y0 = *reinterpret_cast<const uint4*>(by);
        const uint4 y1 = *reinterpret_cast<const uint4*>(by + NCH);
        const uint4 z0 = *reinterpret_cast<const uint4*>(bz);
        const uint4 z1 = *reinterpret_cast<const uint4*>(bz + NCH);

        // ---- interpolate + accumulate in half2 ----
        #define H2(u) (*reinterpret_cast<const __half2*>(&(u)))
        __half2 a0 = __hfma2(w0, __hsub2(H2(x1.x), H2(x0.x)), H2(x0.x));
        __half2 a1 = __hfma2(w0, __hsub2(H2(x1.y), H2(x0.y)), H2(x0.y));
        __half2 a2 = __hfma2(w0, __hsub2(H2(x1.z), H2(x0.z)), H2(x0.z));
        __half2 a3 = __hfma2(w0, __hsub2(H2(x1.w), H2(x0.w)), H2(x0.w));

        a0 = __hadd2(a0, __hfma2(w1, __hsub2(H2(y1.x), H2(y0.x)), H2(y0.x)));
        a1 = __hadd2(a1, __hfma2(w1, __hsub2(H2(y1.y), H2(y0.y)), H2(y0.y)));
        a2 = __hadd2(a2, __hfma2(w1, __hsub2(H2(y1.z), H2(y0.z)), H2(y0.z)));
        a3 = __hadd2(a3, __hfma2(w1, __hsub2(H2(y1.w), H2(y0.w)), H2(y0.w)));

        a0 = __hadd2(a0, __hfma2(w2, __hsub2(H2(z1.x), H2(z0.x)), H2(z0.x)));
        a1 = __hadd2(a1, __hfma2(w2, __hsub2(H2(z1.y), H2(z0.y)), H2(z0.y)));
        a2 = __hadd2(a2, __hfma2(w2, __hsub2(H2(z1.z), H2(z0.z)), H2(z0.z)));
        a3 = __hadd2(a3, __hfma2(w2, __hsub2(H2(z1.w), H2(z0.w)), H2(z0.w)));
        #undef H2

        // ---- fp32 convert + streaming stores (write-once output) ----
        const float2 o0 = __half22float2(a0);
        const float2 o1 = __half22float2(a1);
        const float2 o2 = __half22float2(a2);
        const float2 o3 = __half22float2(a3);

        float* optr = out + (size_t)(p0 + g) * NCH + ch;
        __stcs(reinterpret_cast<float4*>(optr),     make_float4(o0.x, o0.y, o1.x, o1.y));
        __stcs(reinterpret_cast<float4*>(optr + 4), make_float4(o2.x, o2.y, o3.x, o3.y));

        p0 = pn;
        c0 = c0n;  c1 = c1n;  c2 = c2n;
    }
}

extern "C" void kernel_launch(void* const* d_in, const int* in_sizes, int n_in,
                              void* d_out, int out_size)
{
    const float* coords = (const float*)d_in[0];
    const float* xl     = (const float*)d_in[1];
    const float* yl     = (const float*)d_in[2];
    const float* zl     = (const float*)d_in[3];
    const float* grid   = (const float*)d_in[4];
    float*       out    = (float*)d_out;

    const int B = in_sizes[0] / 3;

    cudaFuncSetAttribute(triline_kernel,
                         cudaFuncAttributeMaxDynamicSharedMemorySize,
                         SMEM_BYTES);

    triline_kernel<<<148, THREADS, SMEM_BYTES>>>(coords, xl, yl, zl, grid, out, B);
}

// round 15
// speedup vs baseline: 1.0225x; 1.0225x over previous
#include <cuda_runtime.h>
#include <cuda_fp16.h>

#define NPTS    512
#define NCH     64
#define CHG     32                        // channels per CTA (fp16)
#define THREADS 768
#define WARPS   (THREADS / 32)            // 24
#define U       8                         // points per warp per iteration
#define LINE_HALFS (NPTS * CHG)           // 16384 halves per line slice
#define SMEM_BYTES (3 * LINE_HALFS * 2)   // 98304 B -> 2 CTAs/SM

__global__ __launch_bounds__(THREADS, 2)
void triline_kernel(const float* __restrict__ coords,
                    const float* __restrict__ xl,
                    const float* __restrict__ yl,
                    const float* __restrict__ zl,
                    const float* __restrict__ grid,
                    float* __restrict__ out,
                    int B)
{
    extern __shared__ __half2 smem2[];    // 3 line-slices x 8192 half2

    const int cb = blockIdx.y * CHG;      // channel base: 0 or 32

    // ---- cooperative fill: fp32 global [512][64] slice -> fp16 smem [512][32] ----
    {
        const float* srcs[3] = { xl, yl, zl };
        #pragma unroll
        for (int a = 0; a < 3; a++) {
            __half2* dst = smem2 + a * (LINE_HALFS / 2);
            for (int i = threadIdx.x; i < LINE_HALFS / 4; i += THREADS) {
                const int row  = i >> 3;            // 8 float4 per 32-ch slice row
                const int q    = i & 7;
                const float4 f = *reinterpret_cast<const float4*>(srcs[a] + row * NCH + cb + 4 * q);
                dst[2 * i    ] = __floats2half2_rn(f.x, f.y);
                dst[2 * i + 1] = __floats2half2_rn(f.z, f.w);
            }
        }
    }

    const float g0     = grid[0];
    const float inv_dg = 1.0f / (grid[1] - grid[0]);
    __syncthreads();

    const int lane = threadIdx.x & 31;
    const int wid  = threadIdx.x >> 5;
    const int g    = lane >> 2;           // point group 0..7 within warp
    const int ch   = (lane & 3) << 3;     // channel offset in halves (8 ch per lane)

    const __half* sbase = reinterpret_cast<const __half*>(smem2);

    const int stride = gridDim.x * WARPS * U;     // 148*24*8 = 28416
    int p0 = (blockIdx.x * WARPS + wid) * U;

    // Cooperative coord prefetch: lanes 0..23 hold 8 points x 3 axes (one LDG)
    float v = 0.0f;
    if (lane < 3 * U && p0 < B) v = __ldg(coords + 3 * p0 + lane);

    while (p0 < B) {
        const int pn = p0 + stride;
        float vn = 0.0f;
        if (lane < 3 * U && pn < B) vn = __ldg(coords + 3 * pn + lane);

        __half2 a0, a1, a2, a3;           // 8 channels as 4 half2

        #pragma unroll
        for (int a = 0; a < 3; a++) {
            const float c   = __shfl_sync(0xffffffffu, v, 3 * g + a);
            const float pos = (c - g0) * inv_dg;
            int ii = __float2int_rd(pos);
            ii = max(0, min(ii, NPTS - 2));
            const __half2 w2 = __float2half2_rn(pos - (float)ii);

            const __half* base = sbase + a * LINE_HALFS + ii * CHG + ch;
            const uint4 u0 = *reinterpret_cast<const uint4*>(base);        // row ii
            const uint4 u1 = *reinterpret_cast<const uint4*>(base + CHG);  // row ii+1

            #define H2(u) (*reinterpret_cast<const __half2*>(&(u)))
            const __half2 r0 = __hfma2(w2, __hsub2(H2(u1.x), H2(u0.x)), H2(u0.x));
            const __half2 r1 = __hfma2(w2, __hsub2(H2(u1.y), H2(u0.y)), H2(u0.y));
            const __half2 r2 = __hfma2(w2, __hsub2(H2(u1.z), H2(u0.z)), H2(u0.z));
            const __half2 r3 = __hfma2(w2, __hsub2(H2(u1.w), H2(u0.w)), H2(u0.w));
            #undef H2

            if (a == 0) { a0 = r0; a1 = r1; a2 = r2; a3 = r3; }
            else {
                a0 = __hadd2(a0, r0);
                a1 = __hadd2(a1, r1);
                a2 = __hadd2(a2, r2);
                a3 = __hadd2(a3, r3);
            }
        }

        // fp32 convert + stores: 4 lanes x 32B = 128B contiguous per point
        const float2 o0 = __half22float2(a0);
        const float2 o1 = __half22float2(a1);
        const float2 o2 = __half22float2(a2);
        const float2 o3 = __half22float2(a3);

        float* optr = out + (size_t)(p0 + g) * NCH + cb + ch;
        *reinterpret_cast<float4*>(optr)     = make_float4(o0.x, o0.y, o1.x, o1.y);
        *reinterpret_cast<float4*>(optr + 4) = make_float4(o2.x, o2.y, o3.x, o3.y);

        p0 = pn;
        v  = vn;
    }
}

extern "C" void kernel_launch(void* const* d_in, const int* in_sizes, int n_in,
                              void* d_out, int out_size)
{
    const float* coords = (const float*)d_in[0];
    const float* xl     = (const float*)d_in[1];
    const float* yl     = (const float*)d_in[2];
    const float* zl     = (const float*)d_in[3];
    const float* grid   = (const float*)d_in[4];
    float*       out    = (float*)d_out;

    const int B = in_sizes[0] / 3;

    cudaFuncSetAttribute(triline_kernel,
                         cudaFuncAttributeMaxDynamicSharedMemorySize,
                         SMEM_BYTES);

    dim3 gridDim(148, 2);   // 296 CTAs = 2 CTAs/SM (one channel half each), 1 wave
    triline_kernel<<<gridDim, THREADS, SMEM_BYTES>>>(coords, xl, yl, zl, grid, out, B);
}